// round 12
// baseline (speedup 1.0000x reference)
#include <cuda_runtime.h>
#include <math.h>

#define BB   8
#define LL   2016
#define HH   4
#define DKK  32
#define DD   256
#define FCC  64
#define NLL  3
#define BL   (BB*LL)      // 16128
#define HD   (HH*DKK)     // 128
#define BHH  (BB*HH)      // 32
#define SCALE 0.0625f     // 1/sqrt(256)
#define EPSV  1e-5f
#define LOG2E 1.4426950408889634f

// ---------------- scratch (device globals: no allocation allowed) ----------
__device__ float g_h [BL*DD];
__device__ float g_q [BL*HD];
__device__ float g_k [BL*HD];
__device__ float g_v [BL*HD];
__device__ float g_o [BL*HD];
__device__ float g_t1[BL*DD];
__device__ float g_ff[BL*FCC];

// ---------------- tf32 helpers --------------------------------------------
__device__ __forceinline__ unsigned f2tf(float f) {
    unsigned u;
    asm("cvt.rna.tf32.f32 %0, %1;" : "=r"(u) : "f"(f));
    return u;
}

__device__ __forceinline__ float ex2(float x) {
    float r;
    asm("ex2.approx.f32 %0, %1;" : "=f"(r) : "f"(x));
    return r;
}

__device__ __forceinline__ void mma_tf32(float* d, const unsigned* a, const unsigned* b) {
    asm("mma.sync.aligned.m16n8k8.row.col.f32.tf32.tf32.f32 "
        "{%0,%1,%2,%3},{%4,%5,%6,%7},{%8,%9},{%0,%1,%2,%3};"
        : "+f"(d[0]), "+f"(d[1]), "+f"(d[2]), "+f"(d[3])
        : "r"(a[0]), "r"(a[1]), "r"(a[2]), "r"(a[3]),
          "r"(b[0]), "r"(b[1]));
}

__device__ __forceinline__ void split4(float4 f, uint4& hi, uint4& lo) {
    hi.x = f2tf(f.x); hi.y = f2tf(f.y); hi.z = f2tf(f.z); hi.w = f2tf(f.w);
    lo.x = f2tf(f.x - __uint_as_float(hi.x));
    lo.y = f2tf(f.y - __uint_as_float(hi.y));
    lo.z = f2tf(f.z - __uint_as_float(hi.z));
    lo.w = f2tf(f.w - __uint_as_float(hi.w));
}

__device__ __forceinline__ uint4 tf4(float4 f) {
    uint4 u;
    u.x = f2tf(f.x); u.y = f2tf(f.y); u.z = f2tf(f.z); u.w = f2tf(f.w);
    return u;
}

// ---------------- input projection: h = x @ in_w + in_b (K=2) -------------
__global__ void k_input(const float* __restrict__ x, const float* __restrict__ w,
                        const float* __restrict__ b, float* __restrict__ h) {
    int idx = blockIdx.x * 256 + threadIdx.x;
    int d = idx & (DD - 1);
    int r = idx >> 8;
    h[idx] = fmaf(x[2*r], w[d], fmaf(x[2*r+1], w[DD + d], b[d]));
}

// ------- 2-term split-tf32 GEMM, register-prefetch double-buffered ---------
// block tile 128x64, 8 warps 4x2, warp tile 32x32. M%128==0, N%64==0, K%32==0
template<bool RELU>
__global__ void __launch_bounds__(256) k_gemm_mma(
        const float* __restrict__ A, const float* __restrict__ W,
        const float* __restrict__ bias, float* __restrict__ C,
        int M, int N, int K) {
    __shared__ unsigned AsH[128*36], AsL[128*36];
    __shared__ unsigned WsH[32*72];
    int tid = threadIdx.x;
    int w = tid >> 5, lane = tid & 31, g = lane >> 2, t = lane & 3;
    int wm = w >> 1, wn = w & 1;
    int m0 = blockIdx.y * 128, n0 = blockIdx.x * 64;
    float acc[2][4][4] = {};
    float4 pA[4], pW[2];
    #pragma unroll
    for (int j = 0; j < 4; j++) {
        int i = tid + j*256; int r = i >> 3, c4 = (i & 7)*4;
        pA[j] = *(const float4*)&A[(size_t)(m0 + r) * K + c4];
    }
    #pragma unroll
    for (int j = 0; j < 2; j++) {
        int i = tid + j*256; int kk = i >> 4, c4 = (i & 15)*4;
        pW[j] = *(const float4*)&W[(size_t)kk * N + n0 + c4];
    }
    for (int k0 = 0; k0 < K; k0 += 32) {
        #pragma unroll
        for (int j = 0; j < 4; j++) {
            int i = tid + j*256; int r = i >> 3, c4 = (i & 7)*4;
            uint4 hi, lo; split4(pA[j], hi, lo);
            *(uint4*)&AsH[r*36 + c4] = hi;
            *(uint4*)&AsL[r*36 + c4] = lo;
        }
        #pragma unroll
        for (int j = 0; j < 2; j++) {
            int i = tid + j*256; int kk = i >> 4, c4 = (i & 15)*4;
            *(uint4*)&WsH[kk*72 + c4] = tf4(pW[j]);
        }
        __syncthreads();
        if (k0 + 32 < K) {
            #pragma unroll
            for (int j = 0; j < 4; j++) {
                int i = tid + j*256; int r = i >> 3, c4 = (i & 7)*4;
                pA[j] = *(const float4*)&A[(size_t)(m0 + r) * K + k0 + 32 + c4];
            }
            #pragma unroll
            for (int j = 0; j < 2; j++) {
                int i = tid + j*256; int kk = i >> 4, c4 = (i & 15)*4;
                pW[j] = *(const float4*)&W[(size_t)(k0 + 32 + kk) * N + n0 + c4];
            }
        }
        #pragma unroll
        for (int kk = 0; kk < 4; kk++) {
            unsigned aH[2][4], aL[2][4];
            #pragma unroll
            for (int mi = 0; mi < 2; mi++) {
                int ar = wm*32 + mi*16;
                aH[mi][0] = AsH[(ar + g    )*36 + kk*8 + t];
                aH[mi][1] = AsH[(ar + g + 8)*36 + kk*8 + t];
                aH[mi][2] = AsH[(ar + g    )*36 + kk*8 + t + 4];
                aH[mi][3] = AsH[(ar + g + 8)*36 + kk*8 + t + 4];
                aL[mi][0] = AsL[(ar + g    )*36 + kk*8 + t];
                aL[mi][1] = AsL[(ar + g + 8)*36 + kk*8 + t];
                aL[mi][2] = AsL[(ar + g    )*36 + kk*8 + t + 4];
                aL[mi][3] = AsL[(ar + g + 8)*36 + kk*8 + t + 4];
            }
            #pragma unroll
            for (int nt = 0; nt < 4; nt++) {
                unsigned bH[2];
                int nc = wn*32 + nt*8 + g;
                bH[0] = WsH[(kk*8 + t    )*72 + nc];
                bH[1] = WsH[(kk*8 + t + 4)*72 + nc];
                #pragma unroll
                for (int mi = 0; mi < 2; mi++) {
                    mma_tf32(acc[mi][nt], aL[mi], bH);
                    mma_tf32(acc[mi][nt], aH[mi], bH);
                }
            }
        }
        __syncthreads();
    }
    #pragma unroll
    for (int mi = 0; mi < 2; mi++) {
        #pragma unroll
        for (int nt = 0; nt < 4; nt++) {
            int col = n0 + wn*32 + nt*8 + t*2;
            int r0  = m0 + wm*32 + mi*16 + g;
            float b0v = bias[col], b1v = bias[col + 1];
            float c00 = acc[mi][nt][0] + b0v, c01 = acc[mi][nt][1] + b1v;
            float c10 = acc[mi][nt][2] + b0v, c11 = acc[mi][nt][3] + b1v;
            if (RELU) {
                c00 = fmaxf(c00, 0.f); c01 = fmaxf(c01, 0.f);
                c10 = fmaxf(c10, 0.f); c11 = fmaxf(c11, 0.f);
            }
            C[(size_t)r0*N + col]     = c00; C[(size_t)r0*N + col + 1]     = c01;
            C[(size_t)(r0+8)*N + col] = c10; C[(size_t)(r0+8)*N + col + 1] = c11;
        }
    }
}

// ------- fused QKV: 2-term split, register-prefetch double-buffered --------
// block 64x64, 8 warps 4x2 (warp tile 16x32), grid (HD/64=2, BL/64)
__global__ void __launch_bounds__(256) k_qkv(
        const float* __restrict__ A,
        const float* __restrict__ qw, const float* __restrict__ qb2,
        const float* __restrict__ kw, const float* __restrict__ kb2,
        const float* __restrict__ vw, const float* __restrict__ vb2,
        float* __restrict__ q, float* __restrict__ k, float* __restrict__ v) {
    __shared__ unsigned AsH[64*36], AsL[64*36];
    __shared__ unsigned WsH[3*32*72];
    int tid = threadIdx.x;
    int w = tid >> 5, lane = tid & 31, g = lane >> 2, t = lane & 3;
    int wm = w >> 1, wn = w & 1;
    int m0 = blockIdx.y * 64, n0 = blockIdx.x * 64;
    const float* Wp[3] = {qw, kw, vw};
    float acc[3][4][4] = {};
    float4 pA[2], pW[6];
    #pragma unroll
    for (int j = 0; j < 2; j++) {
        int i = tid + j*256; int r = i >> 3, c4 = (i & 7)*4;
        pA[j] = *(const float4*)&A[(size_t)(m0 + r) * DD + c4];
    }
    #pragma unroll
    for (int j = 0; j < 6; j++) {
        int i = tid + j*256; int o = i >> 9, jj = i & 511;
        int kk = jj >> 4, c4 = (jj & 15)*4;
        pW[j] = *(const float4*)&Wp[o][(size_t)kk * HD + n0 + c4];
    }
    for (int k0 = 0; k0 < DD; k0 += 32) {
        #pragma unroll
        for (int j = 0; j < 2; j++) {
            int i = tid + j*256; int r = i >> 3, c4 = (i & 7)*4;
            uint4 hi, lo; split4(pA[j], hi, lo);
            *(uint4*)&AsH[r*36 + c4] = hi;
            *(uint4*)&AsL[r*36 + c4] = lo;
        }
        #pragma unroll
        for (int j = 0; j < 6; j++) {
            int i = tid + j*256; int o = i >> 9, jj = i & 511;
            int kk = jj >> 4, c4 = (jj & 15)*4;
            *(uint4*)&WsH[o*2304 + kk*72 + c4] = tf4(pW[j]);
        }
        __syncthreads();
        if (k0 + 32 < DD) {
            #pragma unroll
            for (int j = 0; j < 2; j++) {
                int i = tid + j*256; int r = i >> 3, c4 = (i & 7)*4;
                pA[j] = *(const float4*)&A[(size_t)(m0 + r) * DD + k0 + 32 + c4];
            }
            #pragma unroll
            for (int j = 0; j < 6; j++) {
                int i = tid + j*256; int o = i >> 9, jj = i & 511;
                int kk = jj >> 4, c4 = (jj & 15)*4;
                pW[j] = *(const float4*)&Wp[o][(size_t)(k0 + 32 + kk) * HD + n0 + c4];
            }
        }
        #pragma unroll
        for (int kk = 0; kk < 4; kk++) {
            unsigned aH[4], aL[4];
            int ar = wm*16;
            aH[0] = AsH[(ar + g    )*36 + kk*8 + t];
            aH[1] = AsH[(ar + g + 8)*36 + kk*8 + t];
            aH[2] = AsH[(ar + g    )*36 + kk*8 + t + 4];
            aH[3] = AsH[(ar + g + 8)*36 + kk*8 + t + 4];
            aL[0] = AsL[(ar + g    )*36 + kk*8 + t];
            aL[1] = AsL[(ar + g + 8)*36 + kk*8 + t];
            aL[2] = AsL[(ar + g    )*36 + kk*8 + t + 4];
            aL[3] = AsL[(ar + g + 8)*36 + kk*8 + t + 4];
            #pragma unroll
            for (int o = 0; o < 3; o++) {
                #pragma unroll
                for (int nt = 0; nt < 4; nt++) {
                    unsigned bH[2];
                    int nc = o*2304 + wn*32 + nt*8 + g;
                    bH[0] = WsH[(kk*8 + t    )*72 + nc];
                    bH[1] = WsH[(kk*8 + t + 4)*72 + nc];
                    mma_tf32(acc[o][nt], aL, bH);
                    mma_tf32(acc[o][nt], aH, bH);
                }
            }
        }
        __syncthreads();
    }
    float* Co[3] = {q, k, v};
    const float* Bo[3] = {qb2, kb2, vb2};
    #pragma unroll
    for (int o = 0; o < 3; o++) {
        #pragma unroll
        for (int nt = 0; nt < 4; nt++) {
            int col = n0 + wn*32 + nt*8 + t*2;
            int r0  = m0 + wm*16 + g;
            float b0v = Bo[o][col], b1v = Bo[o][col + 1];
            Co[o][(size_t)r0*HD + col]       = acc[o][nt][0] + b0v;
            Co[o][(size_t)r0*HD + col + 1]   = acc[o][nt][1] + b1v;
            Co[o][(size_t)(r0+8)*HD + col]   = acc[o][nt][2] + b0v;
            Co[o][(size_t)(r0+8)*HD + col+1] = acc[o][nt][3] + b1v;
        }
    }
}

// ------- merged flash attention (no-max softmax), 256 rows/CTA -------------
// grid (8 row-tiles of 256, 32 bh), 512 thr, 16 warps x 16 rows.
// Q frags in registers; P relayout via shuffles; K/V reg-prefetch dbl-buffer.
__global__ void __launch_bounds__(512) k_attn2(
        const float* __restrict__ Q, const float* __restrict__ Kv,
        const float* __restrict__ V, float* __restrict__ P,
        float* __restrict__ O) {
    __shared__ unsigned Ks[128*36];
    __shared__ unsigned Vs[128*40];
    int tid = threadIdx.x;
    int w = tid >> 5, lane = tid & 31, g = lane >> 2, t = lane & 3;
    int l0 = blockIdx.x * 256;
    int bh = blockIdx.y, b = bh >> 2, hh = bh & 3;
    const float* qb = Q  + (size_t)b * LL * HD + hh * DKK;
    const float* kb = Kv + (size_t)b * LL * HD + hh * DKK;
    const float* vb = V  + (size_t)b * LL * HD + hh * DKK;

    int row0 = l0 + w*16 + g;
    int row1 = row0 + 8;
    bool r0ok = row0 < LL, r1ok = row1 < LL;

    unsigned qf[4][4];
    #pragma unroll
    for (int kk = 0; kk < 4; kk++) {
        qf[kk][0] = f2tf(r0ok ? qb[(size_t)row0*HD + kk*8 + t]     : 0.f);
        qf[kk][1] = f2tf(r1ok ? qb[(size_t)row1*HD + kk*8 + t]     : 0.f);
        qf[kk][2] = f2tf(r0ok ? qb[(size_t)row0*HD + kk*8 + t + 4] : 0.f);
        qf[kk][3] = f2tf(r1ok ? qb[(size_t)row1*HD + kk*8 + t + 4] : 0.f);
    }
    const float S2 = SCALE * LOG2E;
    const float4 f0 = make_float4(0.f, 0.f, 0.f, 0.f);

    // ---- phase 0: per-row z = sum exp2(s*S2) (no max: bounded scores) ----
    float z0 = 0.f, z1 = 0.f;
    float4 pk[2];
    #pragma unroll
    for (int j = 0; j < 2; j++) {
        int i = tid + j*512; int r = i >> 3, c4 = (i & 7)*4;
        pk[j] = (r < LL) ? *(const float4*)&kb[(size_t)r * HD + c4] : f0;
    }
    for (int s0 = 0; s0 < LL; s0 += 128) {
        #pragma unroll
        for (int j = 0; j < 2; j++) {
            int i = tid + j*512; int r = i >> 3, c4 = (i & 7)*4;
            *(uint4*)&Ks[r*36 + c4] = tf4(pk[j]);
        }
        __syncthreads();
        if (s0 + 128 < LL) {
            #pragma unroll
            for (int j = 0; j < 2; j++) {
                int i = tid + j*512; int r = i >> 3, c4 = (i & 7)*4;
                int sr = s0 + 128 + r;
                pk[j] = (sr < LL) ? *(const float4*)&kb[(size_t)sr * HD + c4] : f0;
            }
        }
        #pragma unroll
        for (int hf2 = 0; hf2 < 2; hf2++) {
            int sb = s0 + hf2*64;
            float acc[8][4] = {};
            #pragma unroll
            for (int kk = 0; kk < 4; kk++) {
                #pragma unroll
                for (int ni = 0; ni < 8; ni++) {
                    unsigned b2[2];
                    b2[0] = Ks[(hf2*64 + ni*8 + g)*36 + kk*8 + t];
                    b2[1] = Ks[(hf2*64 + ni*8 + g)*36 + kk*8 + t + 4];
                    mma_tf32(acc[ni], qf[kk], b2);
                }
            }
            #pragma unroll
            for (int ni = 0; ni < 8; ni++) {
                if (sb + ni*8 < LL) {
                    z0 += ex2(acc[ni][0]*S2) + ex2(acc[ni][1]*S2);
                    z1 += ex2(acc[ni][2]*S2) + ex2(acc[ni][3]*S2);
                }
            }
        }
        __syncthreads();
    }
    z0 += __shfl_xor_sync(0xffffffffu, z0, 1);
    z0 += __shfl_xor_sync(0xffffffffu, z0, 2);
    z1 += __shfl_xor_sync(0xffffffffu, z1, 1);
    z1 += __shfl_xor_sync(0xffffffffu, z1, 2);
    float inv0 = 1.f / z0, inv1 = 1.f / z1;

    // ---- phase 1: recompute S, write P, accumulate O = P@V ---------------
    float* Pb = P + (size_t)bh * LL * LL;
    float acc2[4][4] = {};
    int srcA = (lane & 0x1C) | (t >> 1);
    bool odd = (t & 1);
    float4 pv[2];
    #pragma unroll
    for (int j = 0; j < 2; j++) {
        int i = tid + j*512; int r = i >> 3, c4 = (i & 7)*4;
        pk[j] = (r < LL) ? *(const float4*)&kb[(size_t)r * HD + c4] : f0;
        pv[j] = (r < LL) ? *(const float4*)&vb[(size_t)r * HD + c4] : f0;
    }
    for (int s0 = 0; s0 < LL; s0 += 128) {
        #pragma unroll
        for (int j = 0; j < 2; j++) {
            int i = tid + j*512; int r = i >> 3, c4 = (i & 7)*4;
            *(uint4*)&Ks[r*36 + c4] = tf4(pk[j]);
            *(uint4*)&Vs[r*40 + c4] = tf4(pv[j]);
        }
        __syncthreads();
        if (s0 + 128 < LL) {
            #pragma unroll
            for (int j = 0; j < 2; j++) {
                int i = tid + j*512; int r = i >> 3, c4 = (i & 7)*4;
                int sr = s0 + 128 + r;
                pk[j] = (sr < LL) ? *(const float4*)&kb[(size_t)sr * HD + c4] : f0;
                pv[j] = (sr < LL) ? *(const float4*)&vb[(size_t)sr * HD + c4] : f0;
            }
        }
        #pragma unroll
        for (int hf2 = 0; hf2 < 2; hf2++) {
            int sb = s0 + hf2*64;
            float acc[8][4] = {};
            #pragma unroll
            for (int kk = 0; kk < 4; kk++) {
                #pragma unroll
                for (int ni = 0; ni < 8; ni++) {
                    unsigned b2[2];
                    b2[0] = Ks[(hf2*64 + ni*8 + g)*36 + kk*8 + t];
                    b2[1] = Ks[(hf2*64 + ni*8 + g)*36 + kk*8 + t + 4];
                    mma_tf32(acc[ni], qf[kk], b2);
                }
            }
            #pragma unroll
            for (int ni = 0; ni < 8; ni++) {
                bool cok = (sb + ni*8) < LL;
                float p0 = cok ? ex2(acc[ni][0]*S2) * inv0 : 0.f;
                float p1 = cok ? ex2(acc[ni][1]*S2) * inv0 : 0.f;
                float p2 = cok ? ex2(acc[ni][2]*S2) * inv1 : 0.f;
                float p3 = cok ? ex2(acc[ni][3]*S2) * inv1 : 0.f;
                if (cok) {
                    size_t cidx = (size_t)(sb + ni*8 + t*2);
                    if (r0ok) *(float2*)&Pb[(size_t)row0*LL + cidx] = make_float2(p0, p1);
                    if (r1ok) *(float2*)&Pb[(size_t)row1*LL + cidx] = make_float2(p2, p3);
                }
                acc[ni][0] = __uint_as_float(f2tf(p0));
                acc[ni][1] = __uint_as_float(f2tf(p1));
                acc[ni][2] = __uint_as_float(f2tf(p2));
                acc[ni][3] = __uint_as_float(f2tf(p3));
            }
            #pragma unroll
            for (int kk = 0; kk < 8; kk++) {
                float x0 = __shfl_sync(0xffffffffu, acc[kk][0], srcA);
                float x1 = __shfl_sync(0xffffffffu, acc[kk][1], srcA);
                float y0 = __shfl_sync(0xffffffffu, acc[kk][2], srcA);
                float y1 = __shfl_sync(0xffffffffu, acc[kk][3], srcA);
                float x0b = __shfl_sync(0xffffffffu, acc[kk][0], srcA + 2);
                float x1b = __shfl_sync(0xffffffffu, acc[kk][1], srcA + 2);
                float y0b = __shfl_sync(0xffffffffu, acc[kk][2], srcA + 2);
                float y1b = __shfl_sync(0xffffffffu, acc[kk][3], srcA + 2);
                unsigned a[4];
                a[0] = __float_as_uint(odd ? x1  : x0);
                a[1] = __float_as_uint(odd ? y1  : y0);
                a[2] = __float_as_uint(odd ? x1b : x0b);
                a[3] = __float_as_uint(odd ? y1b : y0b);
                #pragma unroll
                for (int ni = 0; ni < 4; ni++) {
                    unsigned b2[2];
                    b2[0] = Vs[(hf2*64 + kk*8 + t)*40 + ni*8 + g];
                    b2[1] = Vs[(hf2*64 + kk*8 + t + 4)*40 + ni*8 + g];
                    mma_tf32(acc2[ni], a, b2);
                }
            }
        }
        __syncthreads();
    }
    float* ob = O + (size_t)b * LL * HD + hh * DKK;
    #pragma unroll
    for (int ni = 0; ni < 4; ni++) {
        int c0 = ni*8 + t*2;
        if (r0ok) *(float2*)&ob[(size_t)row0*HD + c0] = make_float2(acc2[ni][0], acc2[ni][1]);
        if (r1ok) *(float2*)&ob[(size_t)row1*HD + c0] = make_float2(acc2[ni][2], acc2[ni][3]);
    }
}

// ---------------- h = LayerNorm(h + add) * g + b (row of 256, float4) ------
__global__ void k_ln(float* __restrict__ h, const float* __restrict__ add,
                     const float* __restrict__ g, const float* __restrict__ bta) {
    int row  = blockIdx.x * 8 + (threadIdx.x >> 5);
    int lane = threadIdx.x & 31;
    float* hp = h + (size_t)row * DD;
    const float* ap = add + (size_t)row * DD;
    float4 v[2]; float s = 0.f;
    #pragma unroll
    for (int i = 0; i < 2; i++) {
        int d = lane*4 + i*128;
        float4 a = *(const float4*)&hp[d];
        float4 c = *(const float4*)&ap[d];
        v[i] = make_float4(a.x + c.x, a.y + c.y, a.z + c.z, a.w + c.w);
        s += v[i].x + v[i].y + v[i].z + v[i].w;
    }
    #pragma unroll
    for (int o = 16; o > 0; o >>= 1) s += __shfl_xor_sync(0xffffffffu, s, o);
    float mean = s * (1.f / DD);
    float var = 0.f;
    #pragma unroll
    for (int i = 0; i < 2; i++) {
        float dx = v[i].x - mean, dy = v[i].y - mean;
        float dz = v[i].z - mean, dw = v[i].w - mean;
        var = fmaf(dx, dx, var); var = fmaf(dy, dy, var);
        var = fmaf(dz, dz, var); var = fmaf(dw, dw, var);
    }
    #pragma unroll
    for (int o = 16; o > 0; o >>= 1) var += __shfl_xor_sync(0xffffffffu, var, o);
    var *= (1.f / DD);
    float r = rsqrtf(var + EPSV);
    #pragma unroll
    for (int i = 0; i < 2; i++) {
        int d = lane*4 + i*128;
        float4 gg = *(const float4*)&g[d];
        float4 bb = *(const float4*)&bta[d];
        float4 o4;
        o4.x = (v[i].x - mean) * r * gg.x + bb.x;
        o4.y = (v[i].y - mean) * r * gg.y + bb.y;
        o4.z = (v[i].z - mean) * r * gg.z + bb.z;
        o4.w = (v[i].w - mean) * r * gg.w + bb.w;
        *(float4*)&hp[d] = o4;
    }
}

// ---------------- final head: out = A(relu'd) @ o2w(256x2) + o2b -----------
__global__ void k_out2(const float* __restrict__ A, const float* __restrict__ w,
                       const float* __restrict__ b, float* __restrict__ out) {
    int row  = blockIdx.x * 8 + (threadIdx.x >> 5);
    int lane = threadIdx.x & 31;
    const float* ap = A + (size_t)row * DD;
    float s0 = 0.f, s1 = 0.f;
    #pragma unroll
    for (int i = 0; i < 8; i++) {
        int d = lane + 32*i;
        float a = ap[d];
        s0 = fmaf(a, w[d*2],     s0);
        s1 = fmaf(a, w[d*2 + 1], s1);
    }
    #pragma unroll
    for (int o = 16; o > 0; o >>= 1) {
        s0 += __shfl_xor_sync(0xffffffffu, s0, o);
        s1 += __shfl_xor_sync(0xffffffffu, s1, o);
    }
    if (lane == 0) {
        out[(size_t)row*2]     = s0 + b[0];
        out[(size_t)row*2 + 1] = s1 + b[1];
    }
}

// ---------------------------------------------------------------------------
extern "C" void kernel_launch(void* const* d_in, const int* in_sizes, int n_in,
                              void* d_out, int out_size) {
    const float* x    = (const float*)d_in[0];
    const float* in_w = (const float*)d_in[1];
    const float* in_b = (const float*)d_in[2];
    const float* qw   = (const float*)d_in[3];
    const float* qb   = (const float*)d_in[4];
    const float* kw   = (const float*)d_in[5];
    const float* kb   = (const float*)d_in[6];
    const float* vw   = (const float*)d_in[7];
    const float* vb   = (const float*)d_in[8];
    const float* ow   = (const float*)d_in[9];
    const float* ob   = (const float*)d_in[10];
    const float* f1w  = (const float*)d_in[11];
    const float* f1b  = (const float*)d_in[12];
    const float* f2w  = (const float*)d_in[13];
    const float* f2b  = (const float*)d_in[14];
    const float* n1g  = (const float*)d_in[15];
    const float* n1b  = (const float*)d_in[16];
    const float* n2g  = (const float*)d_in[17];
    const float* n2b  = (const float*)d_in[18];
    const float* o1w  = (const float*)d_in[19];
    const float* o1b  = (const float*)d_in[20];
    const float* o2w  = (const float*)d_in[21];
    const float* o2b  = (const float*)d_in[22];

    float* out  = (float*)d_out;
    float* attn = out + (size_t)BB * LL * 2;   // attns region: (NL,B,H,L,L)

    float *h, *q, *k, *v, *o, *t1, *ff;
    cudaGetSymbolAddress((void**)&h,  g_h);
    cudaGetSymbolAddress((void**)&q,  g_q);
    cudaGetSymbolAddress((void**)&k,  g_k);
    cudaGetSymbolAddress((void**)&v,  g_v);
    cudaGetSymbolAddress((void**)&o,  g_o);
    cudaGetSymbolAddress((void**)&t1, g_t1);
    cudaGetSymbolAddress((void**)&ff, g_ff);

    // input projection
    k_input<<<(BL*DD)/256, 256>>>(x, in_w, in_b, h);

    const int RT = (LL + 255) / 256;   // 8 row tiles

    for (int i = 0; i < NLL; i++) {
        const float* qwi = qw + (size_t)i * DD * HD;
        const float* qbi = qb + (size_t)i * HD;
        const float* kwi = kw + (size_t)i * DD * HD;
        const float* kbi = kb + (size_t)i * HD;
        const float* vwi = vw + (size_t)i * DD * HD;
        const float* vbi = vb + (size_t)i * HD;
        const float* owi = ow + (size_t)i * HD * DD;
        const float* obi = ob + (size_t)i * DD;
        const float* f1wi = f1w + (size_t)i * DD * FCC;
        const float* f1bi = f1b + (size_t)i * FCC;
        const float* f2wi = f2w + (size_t)i * FCC * DD;
        const float* f2bi = f2b + (size_t)i * DD;

        // fused Q,K,V projection
        k_qkv<<<dim3(HD/64, BL/64), 256>>>(
            h, qwi, qbi, kwi, kbi, vwi, vbi, q, k, v);

        // merged flash attention (stats + P + O), 256 rows/CTA
        float* Si = attn + (size_t)i * BHH * LL * LL;
        k_attn2<<<dim3(RT, BHH), 512>>>(q, k, v, Si, o);

        // output projection + residual LN
        k_gemm_mma<false><<<dim3(DD/64, BL/128), 256>>>(o, owi, obi, t1, BL, DD, HD);
        k_ln<<<BL/8, 256>>>(h, t1, n1g + (size_t)i*DD, n1b + (size_t)i*DD);

        // FFN + residual LN
        k_gemm_mma<true ><<<dim3(FCC/64, BL/128), 256>>>(h, f1wi, f1bi, ff, BL, FCC, DD);
        k_gemm_mma<false><<<dim3(DD/64, BL/128), 256>>>(ff, f2wi, f2bi, t1, BL, DD, FCC);
        k_ln<<<BL/8, 256>>>(h, t1, n2g + (size_t)i*DD, n2b + (size_t)i*DD);
    }

    // final MLP head
    k_gemm_mma<true><<<dim3(DD/64, BL/128), 256>>>(h, o1w, o1b, t1, BL, DD, DD);
    k_out2<<<BL/8, 256>>>(t1, o2w, o2b, out);
}